// round 6
// baseline (speedup 1.0000x reference)
#include <cuda_runtime.h>
#include <cuda_fp16.h>
#include <cstdint>

#define SS 8
#define NN 512
#define CC 128
#define HH 128

// Scratch: channels-last fp16 fmap pyramid per plane + fp32 scaled init feats.
__device__ __half g_P0[(size_t)3 * SS * HH * HH * CC];     // [3*S][128][128][C]
__device__ __half g_P1[(size_t)3 * SS * 64 * 64 * CC];
__device__ __half g_P2[(size_t)3 * SS * 32 * 32 * CC];
__device__ __half g_P3[(size_t)3 * SS * 16 * 16 * CC];
__device__ float  g_T [(size_t)3 * NN * CC];               // t / sqrt(C), fp32

__device__ __forceinline__ float2 h2f(uint32_t u) {
    return __half22float2(*(const __half2*)&u);
}
__device__ __forceinline__ uint32_t f2h2(float a, float b) {
    __half2 h = __floats2half2_rn(a, b);
    return *(uint32_t*)&h;
}

// ---------------------------------------------------------------------------
// Fused transpose + full pyramid build.
// Block = (8x8 pixel tile, frame ps). Reads fp32 [C,H,W] tile once, writes
// channels-last fp16 L0(64px) + L1(16px) + L2(4px) + L3(1px).
// ---------------------------------------------------------------------------
#define TP 130   // padded row (floats) for the 64x128 staging tile

__global__ void __launch_bounds__(256) build_kernel(const float* __restrict__ fxy,
                                                    const float* __restrict__ fyz,
                                                    const float* __restrict__ fxz) {
    __shared__ float tile[64 * TP];    // [pixel][channel], padded
    __shared__ float l1b[16 * TP];
    __shared__ float l2b[4 * TP];

    int ps = blockIdx.y;
    int p = ps >> 3, s = ps & 7;
    const float* src = (p == 0 ? fxy : (p == 1 ? fyz : fxz)) + (size_t)s * CC * HH * HH;

    int tileIdx = blockIdx.x;                 // 0..255
    int h0 = (tileIdx >> 4) << 3;
    int w0 = (tileIdx & 15) << 3;
    int t = threadIdx.x;

    // ---- phase 1: load input tile (float2 per thread-iter) into smem ----
    // 4096 float2 slots: c = lin>>5, r = (lin>>2)&7, j = lin&3  (pix = 8r+2j)
#pragma unroll
    for (int i = 0; i < 16; i++) {
        int lin = i * 256 + t;
        int c = lin >> 5;
        int r = (lin >> 2) & 7;
        int j = lin & 3;
        float2 v = *(const float2*)(src + (size_t)c * (HH * HH) + (h0 + r) * HH + w0 + 2 * j);
        int pix = r * 8 + 2 * j;
        tile[pix * TP + c] = v.x;
        tile[(pix + 1) * TP + c] = v.y;
    }
    __syncthreads();

    // ---- phase 2: write L0 (channels-last fp16) ----
    {
        __half* dst = g_P0 + (size_t)ps * HH * HH * CC;
#pragma unroll
        for (int i = 0; i < 16; i++) {
            int lin = i * 256 + t;            // 4096 half2 slots
            int pix = lin >> 6;
            int cp = lin & 63;
            float2 v = *(const float2*)(tile + pix * TP + 2 * cp);
            int hh = h0 + (pix >> 3), ww = w0 + (pix & 7);
            *(uint32_t*)(dst + ((size_t)(hh * HH + ww) << 7) + 2 * cp) = f2h2(v.x, v.y);
        }
    }

    // ---- phase 3: L1 = 2x2 avg of tile ----
    {
        __half* dst = g_P1 + (size_t)ps * 64 * 64 * CC;
        int h1 = h0 >> 1, w1 = w0 >> 1;
#pragma unroll
        for (int i = 0; i < 4; i++) {
            int lin = i * 256 + t;            // 1024 half2 slots
            int pp = lin >> 6;                // 0..15
            int cp = lin & 63;
            int py = pp >> 2, px = pp & 3;
            int pixA = (2 * py) * 8 + 2 * px;
            float2 a = *(const float2*)(tile + pixA * TP + 2 * cp);
            float2 b = *(const float2*)(tile + (pixA + 1) * TP + 2 * cp);
            float2 c = *(const float2*)(tile + (pixA + 8) * TP + 2 * cp);
            float2 d = *(const float2*)(tile + (pixA + 9) * TP + 2 * cp);
            float vx = (a.x + b.x + c.x + d.x) * 0.25f;
            float vy = (a.y + b.y + c.y + d.y) * 0.25f;
            l1b[pp * TP + 2 * cp] = vx;
            l1b[pp * TP + 2 * cp + 1] = vy;
            *(uint32_t*)(dst + ((size_t)((h1 + py) * 64 + w1 + px) << 7) + 2 * cp) = f2h2(vx, vy);
        }
    }
    __syncthreads();

    // ---- phase 4: L2 = 2x2 avg of L1 ----
    {
        __half* dst = g_P2 + (size_t)ps * 32 * 32 * CC;
        int h2 = h0 >> 2, w2 = w0 >> 2;
        int pp = t >> 6;                      // 0..3 (256 half2 slots)
        int cp = t & 63;
        int py = pp >> 1, px = pp & 1;
        int ppA = (2 * py) * 4 + 2 * px;
        float2 a = *(const float2*)(l1b + ppA * TP + 2 * cp);
        float2 b = *(const float2*)(l1b + (ppA + 1) * TP + 2 * cp);
        float2 c = *(const float2*)(l1b + (ppA + 4) * TP + 2 * cp);
        float2 d = *(const float2*)(l1b + (ppA + 5) * TP + 2 * cp);
        float vx = (a.x + b.x + c.x + d.x) * 0.25f;
        float vy = (a.y + b.y + c.y + d.y) * 0.25f;
        l2b[pp * TP + 2 * cp] = vx;
        l2b[pp * TP + 2 * cp + 1] = vy;
        *(uint32_t*)(dst + ((size_t)((h2 + py) * 32 + w2 + px) << 7) + 2 * cp) = f2h2(vx, vy);
    }
    __syncthreads();

    // ---- phase 5: L3 = 2x2 avg of L2 (one pixel) ----
    if (t < 64) {
        __half* dst = g_P3 + (size_t)ps * 16 * 16 * CC;
        int h3 = h0 >> 3, w3 = w0 >> 3;
        int cp = t;
        float2 a = *(const float2*)(l2b + 0 * TP + 2 * cp);
        float2 b = *(const float2*)(l2b + 1 * TP + 2 * cp);
        float2 c = *(const float2*)(l2b + 2 * TP + 2 * cp);
        float2 d = *(const float2*)(l2b + 3 * TP + 2 * cp);
        float vx = (a.x + b.x + c.x + d.x) * 0.25f;
        float vy = (a.y + b.y + c.y + d.y) * 0.25f;
        *(uint32_t*)(dst + ((size_t)(h3 * 16 + w3) << 7) + 2 * cp) = f2h2(vx, vy);
    }
}

// ---------------------------------------------------------------------------
// Init track features (fp32 accumulate from fp16 P0), pre-scaled 1/sqrt(C)
// ---------------------------------------------------------------------------
__global__ void init_kernel(const float* __restrict__ coords,
                            const int* __restrict__ qt) {
    int n = blockIdx.x, p = blockIdx.y, c = threadIdx.x;
    float x = coords[n * 3 + 0], y = coords[n * 3 + 1], z = coords[n * 3 + 2];
    float u = (p == 0) ? x : (p == 1 ? y : x);
    float v = (p == 0) ? y : z;
    int f = qt[n];
    const __half* base = g_P0 + (size_t)(p * SS + f) * HH * HH * CC;

    u = fminf(fmaxf(u, 0.f), (float)(HH - 1));
    v = fminf(fmaxf(v, 0.f), (float)(HH - 1));
    int x0 = min(max((int)floorf(u), 0), HH - 2);
    int y0 = min(max((int)floorf(v), 0), HH - 2);
    float wx = u - (float)x0, wy = v - (float)y0;

    const __half* b00 = base + ((size_t)(y0 * HH + x0) << 7);
    float v00 = __half2float(b00[c]);
    float v01 = __half2float(b00[CC + c]);
    float v10 = __half2float(b00[(HH << 7) + c]);
    float v11 = __half2float(b00[(HH << 7) + CC + c]);
    float val = v00 * (1.f - wx) * (1.f - wy) + v01 * wx * (1.f - wy)
              + v10 * (1.f - wx) * wy + v11 * wx * wy;
    g_T[(size_t)(p * NN + n) * CC + c] = val * 0.08838834764831845f; // 1/sqrt(128)
}

// ---------------------------------------------------------------------------
// Main: block = (n, s, p). Warp w computes level w's 8x8 grid of corr dots
// (16 lanes per position, uint4 loads, 4-level shfl reduce). Then all 128
// threads do 196 taps + 128-channel feature sample.
// ---------------------------------------------------------------------------
__global__ void __launch_bounds__(128) main_kernel(const float* __restrict__ coords,
                                                   float* __restrict__ out) {
    int n = blockIdx.x, s = blockIdx.y, p = blockIdx.z;
    int tid = threadIdx.x, lane = tid & 31, w = tid >> 5;
    int ps = p * SS + s;

    const float* cc = coords + (size_t)(s * NN + n) * 3;
    float x = cc[0], y = cc[1], z = cc[2];
    float u = (p == 0) ? x : (p == 1 ? y : x);
    float v = (p == 0) ? y : z;

    __shared__ float sT[CC];
    __shared__ float G[4][64];
    sT[tid] = g_T[(size_t)(p * NN + n) * CC + tid];
    __syncthreads();

    int li = lane & 15;                       // lane within 16-lane group
    float4 tA = ((const float4*)sT)[li * 2];  // channels li*8 .. li*8+7
    float4 tB = ((const float4*)sT)[li * 2 + 1];

    const __half* base0 = g_P0 + (size_t)ps * HH * HH * CC;
    const __half* base1 = g_P1 + (size_t)ps * 64 * 64 * CC;
    const __half* base2 = g_P2 + (size_t)ps * 32 * 32 * CC;
    const __half* base3 = g_P3 + (size_t)ps * 16 * 16 * CC;

    // ---- grid phase: warp w handles level w ----
    {
        const int l = w;
        const int Wl = HH >> l;
        const float sc = 1.0f / (float)(1 << l);
        const __half* base = (l == 0) ? base0 : (l == 1) ? base1 : (l == 2) ? base2 : base3;

        float cx = u * sc, cy = v * sc;
        int bx = (int)floorf(cx), by = (int)floorf(cy);
        int hp = lane >> 4;                   // which of 2 positions this iter

#pragma unroll
        for (int it = 0; it < 32; it++) {
            int pos = it * 2 + hp;            // 0..63
            int gi = pos >> 3, gj = pos & 7;
            int gy = min(max(by - 3 + gi, 0), Wl - 1);
            int gx = min(max(bx - 3 + gj, 0), Wl - 1);
            uint4 raw = *(const uint4*)(base + ((size_t)(gy * Wl + gx) << 7) + (li << 3));
            float2 f0 = h2f(raw.x), f1 = h2f(raw.y), f2 = h2f(raw.z), f3 = h2f(raw.w);
            float dv = f0.x * tA.x + f0.y * tA.y + f1.x * tA.z + f1.y * tA.w
                     + f2.x * tB.x + f2.y * tB.y + f3.x * tB.z + f3.y * tB.w;
            dv += __shfl_xor_sync(0xffffffffu, dv, 8);
            dv += __shfl_xor_sync(0xffffffffu, dv, 4);
            dv += __shfl_xor_sync(0xffffffffu, dv, 2);
            dv += __shfl_xor_sync(0xffffffffu, dv, 1);
            if (li == 0) G[l][pos] = dv;
        }
    }
    __syncthreads();

    float* ob = out + ((size_t)s * NN + n) * 972;

    // ---- tap phase: 196 taps over 128 threads ----
#pragma unroll
    for (int t = tid; t < 196; t += 128) {
        int l = t / 49, k = t % 49;
        int Wl = HH >> l;
        float sc = (l == 0) ? 1.f : (l == 1) ? 0.5f : (l == 2) ? 0.25f : 0.125f;
        float cx = u * sc, cy = v * sc;
        int bx = (int)floorf(cx), by = (int)floorf(cy);
        int kx = k % 7, ky = k / 7;
        float xs = fminf(fmaxf(cx + (float)(kx - 3), 0.f), (float)(Wl - 1));
        float ys = fminf(fmaxf(cy + (float)(ky - 3), 0.f), (float)(Wl - 1));
        int x0 = min(max((int)floorf(xs), 0), Wl - 2);
        int y0 = min(max((int)floorf(ys), 0), Wl - 2);
        float wx = xs - (float)x0, wy = ys - (float)y0;
        int j = x0 - bx + 3;   // in [0,6], j+1 <= 7 (clamp cases verified)
        int i = y0 - by + 3;
        float g00 = G[l][i * 8 + j];
        float g01 = G[l][i * 8 + j + 1];
        float g10 = G[l][i * 8 + 8 + j];
        float g11 = G[l][i * 8 + 8 + j + 1];
        ob[p * 196 + t] = g00 * (1.f - wx) * (1.f - wy) + g01 * wx * (1.f - wy)
                        + g10 * (1.f - wx) * wy + g11 * wx * wy;
    }

    // ---- full-res feature bilinear sample (thread = channel) ----
    {
        float xs = fminf(fmaxf(u, 0.f), (float)(HH - 1));
        float ys = fminf(fmaxf(v, 0.f), (float)(HH - 1));
        int x0 = min(max((int)floorf(xs), 0), HH - 2);
        int y0 = min(max((int)floorf(ys), 0), HH - 2);
        float wx = xs - (float)x0, wy = ys - (float)y0;
        const __half* b00 = base0 + ((size_t)(y0 * HH + x0) << 7);
        float v00 = __half2float(b00[tid]);
        float v01 = __half2float(b00[CC + tid]);
        float v10 = __half2float(b00[(HH << 7) + tid]);
        float v11 = __half2float(b00[(HH << 7) + CC + tid]);
        ob[588 + p * CC + tid] = v00 * (1.f - wx) * (1.f - wy) + v01 * wx * (1.f - wy)
                               + v10 * (1.f - wx) * wy + v11 * wx * wy;
    }
}

// ---------------------------------------------------------------------------
extern "C" void kernel_launch(void* const* d_in, const int* in_sizes, int n_in,
                              void* d_out, int out_size) {
    const float* fxy    = (const float*)d_in[0];
    const float* fyz    = (const float*)d_in[1];
    const float* fxz    = (const float*)d_in[2];
    const float* coords = (const float*)d_in[3];
    const int*   qt     = (const int*)d_in[4];
    float* out = (float*)d_out;

    // 1) fused transpose + fp16 pyramid build
    {
        dim3 grid(256, 3 * SS);
        build_kernel<<<grid, 256>>>(fxy, fyz, fxz);
    }
    // 2) init track features
    {
        dim3 grid(NN, 3);
        init_kernel<<<grid, CC>>>(coords, qt);
    }
    // 3) main correlation + feature sampling
    {
        dim3 grid(NN, SS, 3);
        main_kernel<<<grid, 128>>>(coords, out);
    }
}

// round 7
// speedup vs baseline: 1.0022x; 1.0022x over previous
#include <cuda_runtime.h>
#include <cuda_fp16.h>
#include <cstdint>

#define SS 8
#define NN 512
#define CC 128
#define HH 128

// Scratch: channels-last fp16 fmap pyramid per plane + fp32 scaled init feats.
__device__ __half g_P0[(size_t)3 * SS * HH * HH * CC];     // [3*S][128][128][C]
__device__ __half g_P1[(size_t)3 * SS * 64 * 64 * CC];
__device__ __half g_P2[(size_t)3 * SS * 32 * 32 * CC];
__device__ __half g_P3[(size_t)3 * SS * 16 * 16 * CC];
__device__ float  g_T [(size_t)3 * NN * CC];               // t / sqrt(C), fp32

__device__ __forceinline__ float2 h2f(uint32_t u) {
    return __half22float2(*(const __half2*)&u);
}
__device__ __forceinline__ uint32_t f2h2(float a, float b) {
    __half2 h = __floats2half2_rn(a, b);
    return *(uint32_t*)&h;
}

// ---------------------------------------------------------------------------
// Fused transpose + full pyramid build. Block = (8x8 px tile, frame ps).
// Staging is CHANNEL-major with 65-word stride: tile[c*65 + pix].
//   phase1 STS: warp c-const, pix distinct -> banks (c+pix)%32, <=2-way.
//   later LDS: warp spans channel pairs at fixed pix -> stride 130%32=2, <=2-way.
// ---------------------------------------------------------------------------
#define ST0 65   // L0 staging stride (words) for 64 pixels
#define ST1 17   // L1 staging stride for 16 pixels
#define ST2 5    // L2 staging stride for 4 pixels

__global__ void __launch_bounds__(256) build_kernel(const float* __restrict__ fxy,
                                                    const float* __restrict__ fyz,
                                                    const float* __restrict__ fxz) {
    __shared__ float tile[CC * ST0];   // [channel][pixel(64)]
    __shared__ float l1b[CC * ST1];    // [channel][pixel(16)]
    __shared__ float l2b[CC * ST2];    // [channel][pixel(4)]

    int ps = blockIdx.y;
    int p = ps >> 3, s = ps & 7;
    const float* src = (p == 0 ? fxy : (p == 1 ? fyz : fxz)) + (size_t)s * CC * HH * HH;

    int tileIdx = blockIdx.x;                 // 0..255
    int h0 = (tileIdx >> 4) << 3;
    int w0 = (tileIdx & 15) << 3;
    int t = threadIdx.x;

    // ---- phase 1: load fp32 tile into channel-major staging ----
    // 4096 float2 slots: c = lin>>5 (warp-const), m = lin&31 -> r=m>>2, j=m&3
#pragma unroll
    for (int i = 0; i < 16; i++) {
        int lin = i * 256 + t;
        int c = lin >> 5;
        int m = lin & 31;
        int r = m >> 2, j = m & 3;
        float2 v = *(const float2*)(src + (size_t)c * (HH * HH) + (h0 + r) * HH + w0 + 2 * j);
        int pix = 8 * r + 2 * j;             // even
        tile[c * ST0 + pix] = v.x;
        tile[c * ST0 + pix + 1] = v.y;
    }
    __syncthreads();

    // ---- phase 2: write L0 channels-last fp16 (warp: fixed pixel, cp spans) ----
    {
        __half* dst = g_P0 + (size_t)ps * HH * HH * CC;
#pragma unroll
        for (int i = 0; i < 16; i++) {
            int lin = i * 256 + t;            // 4096 half2 slots
            int pix = lin >> 6;               // warp-const
            int cp = lin & 63;
            float a = tile[(2 * cp) * ST0 + pix];
            float b = tile[(2 * cp + 1) * ST0 + pix];
            int hh = h0 + (pix >> 3), ww = w0 + (pix & 7);
            *(uint32_t*)(dst + ((size_t)(hh * HH + ww) << 7) + 2 * cp) = f2h2(a, b);
        }
    }

    // ---- phase 3: L1 = 2x2 avg; write gmem + stage ----
    {
        __half* dst = g_P1 + (size_t)ps * 64 * 64 * CC;
        int h1 = h0 >> 1, w1 = w0 >> 1;
#pragma unroll
        for (int i = 0; i < 4; i++) {
            int lin = i * 256 + t;            // 1024 half2 slots
            int pp = lin >> 6;                // 0..15, warp-const
            int cp = lin & 63;
            int py = pp >> 2, px = pp & 3;
            int pA = (2 * py) * 8 + 2 * px;
            int c0 = (2 * cp) * ST0, c1 = (2 * cp + 1) * ST0;
            float ax = tile[c0 + pA] + tile[c0 + pA + 1] + tile[c0 + pA + 8] + tile[c0 + pA + 9];
            float ay = tile[c1 + pA] + tile[c1 + pA + 1] + tile[c1 + pA + 8] + tile[c1 + pA + 9];
            float vx = ax * 0.25f, vy = ay * 0.25f;
            l1b[(2 * cp) * ST1 + pp] = vx;
            l1b[(2 * cp + 1) * ST1 + pp] = vy;
            *(uint32_t*)(dst + ((size_t)((h1 + py) * 64 + w1 + px) << 7) + 2 * cp) = f2h2(vx, vy);
        }
    }
    __syncthreads();

    // ---- phase 4: L2 = 2x2 avg of L1 ----
    if (t < 256) {
        __half* dst = g_P2 + (size_t)ps * 32 * 32 * CC;
        int h2 = h0 >> 2, w2 = w0 >> 2;
        int pp = t >> 6;                      // 0..3, warp-const
        int cp = t & 63;
        int py = pp >> 1, px = pp & 1;
        int pA = (2 * py) * 4 + 2 * px;
        int c0 = (2 * cp) * ST1, c1 = (2 * cp + 1) * ST1;
        float ax = l1b[c0 + pA] + l1b[c0 + pA + 1] + l1b[c0 + pA + 4] + l1b[c0 + pA + 5];
        float ay = l1b[c1 + pA] + l1b[c1 + pA + 1] + l1b[c1 + pA + 4] + l1b[c1 + pA + 5];
        float vx = ax * 0.25f, vy = ay * 0.25f;
        l2b[(2 * cp) * ST2 + pp] = vx;
        l2b[(2 * cp + 1) * ST2 + pp] = vy;
        *(uint32_t*)(dst + ((size_t)((h2 + py) * 32 + w2 + px) << 7) + 2 * cp) = f2h2(vx, vy);
    }
    __syncthreads();

    // ---- phase 5: L3 = 2x2 avg of L2 (single pixel) ----
    if (t < 64) {
        __half* dst = g_P3 + (size_t)ps * 16 * 16 * CC;
        int h3 = h0 >> 3, w3 = w0 >> 3;
        int cp = t;
        int c0 = (2 * cp) * ST2, c1 = (2 * cp + 1) * ST2;
        float vx = (l2b[c0] + l2b[c0 + 1] + l2b[c0 + 2] + l2b[c0 + 3]) * 0.25f;
        float vy = (l2b[c1] + l2b[c1 + 1] + l2b[c1 + 2] + l2b[c1 + 3]) * 0.25f;
        *(uint32_t*)(dst + ((size_t)(h3 * 16 + w3) << 7) + 2 * cp) = f2h2(vx, vy);
    }
}

// ---------------------------------------------------------------------------
// Init track features (fp32 accumulate from fp16 P0), pre-scaled 1/sqrt(C)
// ---------------------------------------------------------------------------
__global__ void init_kernel(const float* __restrict__ coords,
                            const int* __restrict__ qt) {
    int n = blockIdx.x, p = blockIdx.y, c = threadIdx.x;
    float x = coords[n * 3 + 0], y = coords[n * 3 + 1], z = coords[n * 3 + 2];
    float u = (p == 0) ? x : (p == 1 ? y : x);
    float v = (p == 0) ? y : z;
    int f = qt[n];
    const __half* base = g_P0 + (size_t)(p * SS + f) * HH * HH * CC;

    u = fminf(fmaxf(u, 0.f), (float)(HH - 1));
    v = fminf(fmaxf(v, 0.f), (float)(HH - 1));
    int x0 = min(max((int)floorf(u), 0), HH - 2);
    int y0 = min(max((int)floorf(v), 0), HH - 2);
    float wx = u - (float)x0, wy = v - (float)y0;

    const __half* b00 = base + ((size_t)(y0 * HH + x0) << 7);
    float v00 = __half2float(b00[c]);
    float v01 = __half2float(b00[CC + c]);
    float v10 = __half2float(b00[(HH << 7) + c]);
    float v11 = __half2float(b00[(HH << 7) + CC + c]);
    float val = v00 * (1.f - wx) * (1.f - wy) + v01 * wx * (1.f - wy)
              + v10 * (1.f - wx) * wy + v11 * wx * wy;
    g_T[(size_t)(p * NN + n) * CC + c] = val * 0.08838834764831845f; // 1/sqrt(128)
}

// ---------------------------------------------------------------------------
// Main: block = (n, s, p) with frame order FLIPPED so the first wave reads the
// frames build wrote last (still L2-resident). Warp w computes level w's 8x8
// grid of corr dots; then all 128 threads do 196 taps + feature sample.
// ---------------------------------------------------------------------------
__global__ void __launch_bounds__(128) main_kernel(const float* __restrict__ coords,
                                                   float* __restrict__ out) {
    int n = blockIdx.x;
    int s = 7 - blockIdx.y;                  // flipped traversal (pure permutation)
    int p = 2 - blockIdx.z;
    int tid = threadIdx.x, lane = tid & 31, w = tid >> 5;
    int ps = p * SS + s;

    const float* cc = coords + (size_t)(s * NN + n) * 3;
    float x = cc[0], y = cc[1], z = cc[2];
    float u = (p == 0) ? x : (p == 1 ? y : x);
    float v = (p == 0) ? y : z;

    __shared__ float sT[CC];
    __shared__ float G[4][64];
    sT[tid] = g_T[(size_t)(p * NN + n) * CC + tid];
    __syncthreads();

    int li = lane & 15;                       // lane within 16-lane group
    float4 tA = ((const float4*)sT)[li * 2];  // channels li*8 .. li*8+7
    float4 tB = ((const float4*)sT)[li * 2 + 1];

    const __half* base0 = g_P0 + (size_t)ps * HH * HH * CC;
    const __half* base1 = g_P1 + (size_t)ps * 64 * 64 * CC;
    const __half* base2 = g_P2 + (size_t)ps * 32 * 32 * CC;
    const __half* base3 = g_P3 + (size_t)ps * 16 * 16 * CC;

    // ---- grid phase: warp w handles level w ----
    {
        const int l = w;
        const int Wl = HH >> l;
        const float sc = 1.0f / (float)(1 << l);
        const __half* base = (l == 0) ? base0 : (l == 1) ? base1 : (l == 2) ? base2 : base3;

        float cx = u * sc, cy = v * sc;
        int bx = (int)floorf(cx), by = (int)floorf(cy);
        int hp = lane >> 4;                   // which of 2 positions this iter

#pragma unroll
        for (int it = 0; it < 32; it++) {
            int pos = it * 2 + hp;            // 0..63
            int gi = pos >> 3, gj = pos & 7;
            int gy = min(max(by - 3 + gi, 0), Wl - 1);
            int gx = min(max(bx - 3 + gj, 0), Wl - 1);
            uint4 raw = *(const uint4*)(base + ((size_t)(gy * Wl + gx) << 7) + (li << 3));
            float2 f0 = h2f(raw.x), f1 = h2f(raw.y), f2 = h2f(raw.z), f3 = h2f(raw.w);
            float dv = f0.x * tA.x + f0.y * tA.y + f1.x * tA.z + f1.y * tA.w
                     + f2.x * tB.x + f2.y * tB.y + f3.x * tB.z + f3.y * tB.w;
            dv += __shfl_xor_sync(0xffffffffu, dv, 8);
            dv += __shfl_xor_sync(0xffffffffu, dv, 4);
            dv += __shfl_xor_sync(0xffffffffu, dv, 2);
            dv += __shfl_xor_sync(0xffffffffu, dv, 1);
            if (li == 0) G[l][pos] = dv;
        }
    }
    __syncthreads();

    float* ob = out + ((size_t)s * NN + n) * 972;

    // ---- tap phase: 196 taps over 128 threads ----
#pragma unroll
    for (int t = tid; t < 196; t += 128) {
        int l = t / 49, k = t % 49;
        int Wl = HH >> l;
        float sc = (l == 0) ? 1.f : (l == 1) ? 0.5f : (l == 2) ? 0.25f : 0.125f;
        float cx = u * sc, cy = v * sc;
        int bx = (int)floorf(cx), by = (int)floorf(cy);
        int kx = k % 7, ky = k / 7;
        float xs = fminf(fmaxf(cx + (float)(kx - 3), 0.f), (float)(Wl - 1));
        float ys = fminf(fmaxf(cy + (float)(ky - 3), 0.f), (float)(Wl - 1));
        int x0 = min(max((int)floorf(xs), 0), Wl - 2);
        int y0 = min(max((int)floorf(ys), 0), Wl - 2);
        float wx = xs - (float)x0, wy = ys - (float)y0;
        int j = x0 - bx + 3;   // in [0,6], j+1 <= 7 (clamp cases verified)
        int i = y0 - by + 3;
        float g00 = G[l][i * 8 + j];
        float g01 = G[l][i * 8 + j + 1];
        float g10 = G[l][i * 8 + 8 + j];
        float g11 = G[l][i * 8 + 8 + j + 1];
        ob[p * 196 + t] = g00 * (1.f - wx) * (1.f - wy) + g01 * wx * (1.f - wy)
                        + g10 * (1.f - wx) * wy + g11 * wx * wy;
    }

    // ---- full-res feature bilinear sample (thread = channel) ----
    {
        float xs = fminf(fmaxf(u, 0.f), (float)(HH - 1));
        float ys = fminf(fmaxf(v, 0.f), (float)(HH - 1));
        int x0 = min(max((int)floorf(xs), 0), HH - 2);
        int y0 = min(max((int)floorf(ys), 0), HH - 2);
        float wx = xs - (float)x0, wy = ys - (float)y0;
        const __half* b00 = base0 + ((size_t)(y0 * HH + x0) << 7);
        float v00 = __half2float(b00[tid]);
        float v01 = __half2float(b00[CC + tid]);
        float v10 = __half2float(b00[(HH << 7) + tid]);
        float v11 = __half2float(b00[(HH << 7) + CC + tid]);
        ob[588 + p * CC + tid] = v00 * (1.f - wx) * (1.f - wy) + v01 * wx * (1.f - wy)
                               + v10 * (1.f - wx) * wy + v11 * wx * wy;
    }
}

// ---------------------------------------------------------------------------
extern "C" void kernel_launch(void* const* d_in, const int* in_sizes, int n_in,
                              void* d_out, int out_size) {
    const float* fxy    = (const float*)d_in[0];
    const float* fyz    = (const float*)d_in[1];
    const float* fxz    = (const float*)d_in[2];
    const float* coords = (const float*)d_in[3];
    const int*   qt     = (const int*)d_in[4];
    float* out = (float*)d_out;

    // 1) fused transpose + fp16 pyramid build
    {
        dim3 grid(256, 3 * SS);
        build_kernel<<<grid, 256>>>(fxy, fyz, fxz);
    }
    // 2) init track features
    {
        dim3 grid(NN, 3);
        init_kernel<<<grid, CC>>>(coords, qt);
    }
    // 3) main correlation + feature sampling
    {
        dim3 grid(NN, SS, 3);
        main_kernel<<<grid, 128>>>(coords, out);
    }
}

// round 8
// speedup vs baseline: 1.1775x; 1.1750x over previous
#include <cuda_runtime.h>
#include <cuda_fp16.h>
#include <cstdint>

#define SS 8
#define NN 512
#define CC 128
#define HH 128

// Scratch: channels-last fp16 fmap pyramid per plane + fp32 scaled init feats.
__device__ __half g_P0[(size_t)3 * SS * HH * HH * CC];     // [3*S][128][128][C]
__device__ __half g_P1[(size_t)3 * SS * 64 * 64 * CC];
__device__ __half g_P2[(size_t)3 * SS * 32 * 32 * CC];
__device__ __half g_P3[(size_t)3 * SS * 16 * 16 * CC];
__device__ float  g_T [(size_t)3 * NN * CC];               // t / sqrt(C), fp32

__device__ __forceinline__ float2 h2f(uint32_t u) {
    return __half22float2(*(const __half2*)&u);
}

// ---------------------------------------------------------------------------
// Fused transpose + L1 pool. Tile = 32 channels x (2 rows x 16 px).
//  phase A: gmem fp32 reads, 1-2 lines per warp-instr (coalesced), STS stride-33.
//  phase B: L0 channels-last fp16 writes (64B/warp), LDS stride-33 conflict-free.
//  phase C: L1 = 2x2 avg -> channels-last fp16 (64B/warp).
// ---------------------------------------------------------------------------
__global__ void __launch_bounds__(256) transposeL1_kernel(const float* __restrict__ fxy,
                                                          const float* __restrict__ fyz,
                                                          const float* __restrict__ fxz) {
    __shared__ float tile[32][33];    // [c][px], px = r*16 + j

    int ps = blockIdx.z;              // p*S + s
    int p = ps >> 3, s = ps & 7;
    const float* src = (p == 0 ? fxy : (p == 1 ? fyz : fxz)) + (size_t)s * CC * HH * HH;

    int c0 = blockIdx.y * 32;
    int mt = blockIdx.x;              // 0..511
    int rp = mt >> 3;                 // row pair 0..63
    int xt = (mt & 7) << 4;           // px base within row
    int t = threadIdx.x, lane = t & 31, w = t >> 5;

    // ---- phase A: load fp32 (warp covers one channel: 2 rows x 16 px) ----
#pragma unroll
    for (int k = 0; k < 4; k++) {
        int c = w * 4 + k;            // local channel 0..31
        int r = lane >> 4;            // row within pair
        int j = lane & 15;
        tile[c][r * 16 + j] = src[(size_t)(c0 + c) * (HH * HH) + (2 * rp + r) * HH + xt + j];
    }
    __syncthreads();

    // ---- phase B: L0 channels-last fp16 (warp: fixed px, lanes span c) ----
    {
        __half* d0 = g_P0 + (size_t)ps * HH * HH * CC;
#pragma unroll
        for (int k = 0; k < 4; k++) {
            int px = w * 4 + k;       // 0..31
            int r = px >> 4, j = px & 15;
            float v = tile[lane][px];
            size_t gpix = (size_t)(2 * rp + r) * HH + xt + j;
            d0[gpix * CC + c0 + lane] = __float2half(v);
        }
    }

    // ---- phase C: L1 = 2x2 avg (8 out px x 32 c; 1 value/thread) ----
    {
        __half* d1 = g_P1 + (size_t)ps * 64 * 64 * CC;
        int j1 = w;                   // out px within tile 0..7
        float v = (tile[lane][2 * j1] + tile[lane][2 * j1 + 1]
                 + tile[lane][16 + 2 * j1] + tile[lane][16 + 2 * j1 + 1]) * 0.25f;
        size_t gpix1 = (size_t)rp * 64 + (xt >> 1) + j1;
        d1[gpix1 * CC + c0 + lane] = __float2half(v);
    }
}

// ---------------------------------------------------------------------------
// Fused L2 + L3 pools from L1. Block = 4x4 L1-pixel tile x all 128 channels.
// ---------------------------------------------------------------------------
__global__ void __launch_bounds__(256) pool23_kernel() {
    __shared__ float s1[16][CC];      // 16 L1 px x 128 c (fp32)
    __shared__ float s2[4][CC];       // 4 L2 px

    int ps = blockIdx.y;
    int b = blockIdx.x;               // 0..255
    int by = b >> 4, bx = b & 15;     // L1 tile origin (by*4, bx*4)
    const __half* src1 = g_P1 + (size_t)ps * 64 * 64 * CC;
    int t = threadIdx.x;

    // load 16 px x 128 c (uint4 = 8 halfs per thread)
    {
        int px = t >> 4;              // 0..15
        int cg = (t & 15) * 8;
        int ly = px >> 2, lx = px & 3;
        const __half* q = src1 + ((size_t)((by * 4 + ly) * 64 + bx * 4 + lx)) * CC + cg;
        uint4 r = *(const uint4*)q;
        float2 f;
        f = h2f(r.x); s1[px][cg + 0] = f.x; s1[px][cg + 1] = f.y;
        f = h2f(r.y); s1[px][cg + 2] = f.x; s1[px][cg + 3] = f.y;
        f = h2f(r.z); s1[px][cg + 4] = f.x; s1[px][cg + 5] = f.y;
        f = h2f(r.w); s1[px][cg + 6] = f.x; s1[px][cg + 7] = f.y;
    }
    __syncthreads();

    // L2: 4 out px x 128 c = 512 values, 2 per thread
    {
        __half* d2 = g_P2 + (size_t)ps * 32 * 32 * CC;
#pragma unroll
        for (int it = 0; it < 2; it++) {
            int lin = it * 256 + t;
            int opx = lin >> 7;       // 0..3
            int c = lin & 127;
            int oy = opx >> 1, ox = opx & 1;
            int pA = (2 * oy) * 4 + 2 * ox;
            float v = (s1[pA][c] + s1[pA + 1][c] + s1[pA + 4][c] + s1[pA + 5][c]) * 0.25f;
            s2[opx][c] = v;
            d2[((size_t)((by * 2 + oy) * 32 + bx * 2 + ox)) * CC + c] = __float2half(v);
        }
    }
    __syncthreads();

    // L3: 1 px x 128 c
    if (t < 128) {
        __half* d3 = g_P3 + (size_t)ps * 16 * 16 * CC;
        float v = (s2[0][t] + s2[1][t] + s2[2][t] + s2[3][t]) * 0.25f;
        d3[((size_t)(by * 16 + bx)) * CC + t] = __float2half(v);
    }
}

// ---------------------------------------------------------------------------
// Init track features (fp32 accumulate from fp16 P0), pre-scaled 1/sqrt(C)
// ---------------------------------------------------------------------------
__global__ void init_kernel(const float* __restrict__ coords,
                            const int* __restrict__ qt) {
    int n = blockIdx.x, p = blockIdx.y, c = threadIdx.x;
    float x = coords[n * 3 + 0], y = coords[n * 3 + 1], z = coords[n * 3 + 2];
    float u = (p == 0) ? x : (p == 1 ? y : x);
    float v = (p == 0) ? y : z;
    int f = qt[n];
    const __half* base = g_P0 + (size_t)(p * SS + f) * HH * HH * CC;

    u = fminf(fmaxf(u, 0.f), (float)(HH - 1));
    v = fminf(fmaxf(v, 0.f), (float)(HH - 1));
    int x0 = min(max((int)floorf(u), 0), HH - 2);
    int y0 = min(max((int)floorf(v), 0), HH - 2);
    float wx = u - (float)x0, wy = v - (float)y0;

    const __half* b00 = base + ((size_t)(y0 * HH + x0) << 7);
    float v00 = __half2float(b00[c]);
    float v01 = __half2float(b00[CC + c]);
    float v10 = __half2float(b00[(HH << 7) + c]);
    float v11 = __half2float(b00[(HH << 7) + CC + c]);
    float val = v00 * (1.f - wx) * (1.f - wy) + v01 * wx * (1.f - wy)
              + v10 * (1.f - wx) * wy + v11 * wx * wy;
    g_T[(size_t)(p * NN + n) * CC + c] = val * 0.08838834764831845f; // 1/sqrt(128)
}

// ---------------------------------------------------------------------------
// Main: block = (n, s, p), frame order flipped for L2-tail reuse. Warp w
// computes level w's 8x8 grid of corr dots; then 196 taps + feature sample.
// ---------------------------------------------------------------------------
__global__ void __launch_bounds__(128) main_kernel(const float* __restrict__ coords,
                                                   float* __restrict__ out) {
    int n = blockIdx.x;
    int s = 7 - blockIdx.y;
    int p = 2 - blockIdx.z;
    int tid = threadIdx.x, lane = tid & 31, w = tid >> 5;
    int ps = p * SS + s;

    const float* cc = coords + (size_t)(s * NN + n) * 3;
    float x = cc[0], y = cc[1], z = cc[2];
    float u = (p == 0) ? x : (p == 1 ? y : x);
    float v = (p == 0) ? y : z;

    __shared__ float sT[CC];
    __shared__ float G[4][64];
    sT[tid] = g_T[(size_t)(p * NN + n) * CC + tid];
    __syncthreads();

    int li = lane & 15;
    float4 tA = ((const float4*)sT)[li * 2];
    float4 tB = ((const float4*)sT)[li * 2 + 1];

    const __half* base0 = g_P0 + (size_t)ps * HH * HH * CC;
    const __half* base1 = g_P1 + (size_t)ps * 64 * 64 * CC;
    const __half* base2 = g_P2 + (size_t)ps * 32 * 32 * CC;
    const __half* base3 = g_P3 + (size_t)ps * 16 * 16 * CC;

    {
        const int l = w;
        const int Wl = HH >> l;
        const float sc = 1.0f / (float)(1 << l);
        const __half* base = (l == 0) ? base0 : (l == 1) ? base1 : (l == 2) ? base2 : base3;

        float cx = u * sc, cy = v * sc;
        int bx = (int)floorf(cx), by = (int)floorf(cy);
        int hp = lane >> 4;

#pragma unroll
        for (int it = 0; it < 32; it++) {
            int pos = it * 2 + hp;
            int gi = pos >> 3, gj = pos & 7;
            int gy = min(max(by - 3 + gi, 0), Wl - 1);
            int gx = min(max(bx - 3 + gj, 0), Wl - 1);
            uint4 raw = *(const uint4*)(base + ((size_t)(gy * Wl + gx) << 7) + (li << 3));
            float2 f0 = h2f(raw.x), f1 = h2f(raw.y), f2 = h2f(raw.z), f3 = h2f(raw.w);
            float dv = f0.x * tA.x + f0.y * tA.y + f1.x * tA.z + f1.y * tA.w
                     + f2.x * tB.x + f2.y * tB.y + f3.x * tB.z + f3.y * tB.w;
            dv += __shfl_xor_sync(0xffffffffu, dv, 8);
            dv += __shfl_xor_sync(0xffffffffu, dv, 4);
            dv += __shfl_xor_sync(0xffffffffu, dv, 2);
            dv += __shfl_xor_sync(0xffffffffu, dv, 1);
            if (li == 0) G[l][pos] = dv;
        }
    }
    __syncthreads();

    float* ob = out + ((size_t)s * NN + n) * 972;

#pragma unroll
    for (int t = tid; t < 196; t += 128) {
        int l = t / 49, k = t % 49;
        int Wl = HH >> l;
        float sc = (l == 0) ? 1.f : (l == 1) ? 0.5f : (l == 2) ? 0.25f : 0.125f;
        float cx = u * sc, cy = v * sc;
        int bx = (int)floorf(cx), by = (int)floorf(cy);
        int kx = k % 7, ky = k / 7;
        float xs = fminf(fmaxf(cx + (float)(kx - 3), 0.f), (float)(Wl - 1));
        float ys = fminf(fmaxf(cy + (float)(ky - 3), 0.f), (float)(Wl - 1));
        int x0 = min(max((int)floorf(xs), 0), Wl - 2);
        int y0 = min(max((int)floorf(ys), 0), Wl - 2);
        float wx = xs - (float)x0, wy = ys - (float)y0;
        int j = x0 - bx + 3;
        int i = y0 - by + 3;
        float g00 = G[l][i * 8 + j];
        float g01 = G[l][i * 8 + j + 1];
        float g10 = G[l][i * 8 + 8 + j];
        float g11 = G[l][i * 8 + 8 + j + 1];
        ob[p * 196 + t] = g00 * (1.f - wx) * (1.f - wy) + g01 * wx * (1.f - wy)
                        + g10 * (1.f - wx) * wy + g11 * wx * wy;
    }

    {
        float xs = fminf(fmaxf(u, 0.f), (float)(HH - 1));
        float ys = fminf(fmaxf(v, 0.f), (float)(HH - 1));
        int x0 = min(max((int)floorf(xs), 0), HH - 2);
        int y0 = min(max((int)floorf(ys), 0), HH - 2);
        float wx = xs - (float)x0, wy = ys - (float)y0;
        const __half* b00 = base0 + ((size_t)(y0 * HH + x0) << 7);
        float v00 = __half2float(b00[tid]);
        float v01 = __half2float(b00[CC + tid]);
        float v10 = __half2float(b00[(HH << 7) + tid]);
        float v11 = __half2float(b00[(HH << 7) + CC + tid]);
        ob[588 + p * CC + tid] = v00 * (1.f - wx) * (1.f - wy) + v01 * wx * (1.f - wy)
                               + v10 * (1.f - wx) * wy + v11 * wx * wy;
    }
}

// ---------------------------------------------------------------------------
extern "C" void kernel_launch(void* const* d_in, const int* in_sizes, int n_in,
                              void* d_out, int out_size) {
    const float* fxy    = (const float*)d_in[0];
    const float* fyz    = (const float*)d_in[1];
    const float* fxz    = (const float*)d_in[2];
    const float* coords = (const float*)d_in[3];
    const int*   qt     = (const int*)d_in[4];
    float* out = (float*)d_out;

    // 1) fused transpose + L0/L1 (channels-last fp16)
    {
        dim3 grid(512, CC / 32, 3 * SS);
        transposeL1_kernel<<<grid, 256>>>(fxy, fyz, fxz);
    }
    // 2) fused L2 + L3 pools
    {
        dim3 grid(256, 3 * SS);
        pool23_kernel<<<grid, 256>>>();
    }
    // 3) init track features
    {
        dim3 grid(NN, 3);
        init_kernel<<<grid, CC>>>(coords, qt);
    }
    // 4) main correlation + feature sampling
    {
        dim3 grid(NN, SS, 3);
        main_kernel<<<grid, 128>>>(coords, out);
    }
}